// round 5
// baseline (speedup 1.0000x reference)
#include <cuda_runtime.h>
#include <cuda_bf16.h>

// Problem constants: B=2048, T=512, I=4, H=64, O=4
#define TT 512
#define BB 2048
#define HH 64
#define GG 256   // 4*H gates
#define OO 4
#define NB 7     // batch rows per block
#define GRID 296 // 2 blocks per SM on 148 SMs
#define NT 256   // threads: 128 gate-pairs x 2 K-halves

// ---- packed fp32x2 ops (Blackwell) ----
__device__ __forceinline__ void fma2(unsigned long long &a, unsigned long long w, unsigned long long h){
    asm("fma.rn.f32x2 %0, %1, %2, %0;" : "+l"(a) : "l"(w), "l"(h));
}
__device__ __forceinline__ unsigned long long add2(unsigned long long a, unsigned long long b){
    unsigned long long r; asm("add.rn.f32x2 %0, %1, %2;" : "=l"(r) : "l"(a), "l"(b)); return r;
}
__device__ __forceinline__ float2 unpack2(unsigned long long v){
    float2 r; asm("mov.b64 {%0, %1}, %2;" : "=f"(r.x), "=f"(r.y) : "l"(v)); return r;
}
__device__ __forceinline__ unsigned long long pack2(float lo, float hi){
    unsigned long long r; asm("mov.b64 %0, {%1, %2};" : "=l"(r) : "f"(lo), "f"(hi)); return r;
}
// ---- native MUFU tanh + sigmoid via tanh ----
__device__ __forceinline__ float tanh_ap(float x){
    float r; asm("tanh.approx.f32 %0, %1;" : "=f"(r) : "f"(x)); return r;
}
__device__ __forceinline__ float sig_ap(float x){
    return __fmaf_rn(0.5f, tanh_ap(0.5f * x), 0.5f);
}

__global__ void __launch_bounds__(NT, 2) lstm_fused_kernel(
    const float* __restrict__ x,     // [B, T, I]
    const float* __restrict__ W_ih,  // [4H, I]
    const float* __restrict__ W_hh,  // [4H, H]
    const float* __restrict__ b_ih,  // [4H]
    const float* __restrict__ b_hh,  // [4H]
    const float* __restrict__ W_fc,  // [O, H]
    const float* __restrict__ b_fc,  // [O]
    float* __restrict__ out)         // [1, B, O]
{
    __shared__ __align__(16) float h_sh[NB][HH];     // hidden state
    __shared__ __align__(16) float g_sh[NB][GG];     // pre-activation gates
    __shared__ __align__(16) float4 x_sh[2][NB];     // double-buffered x_t

    const int tid   = threadIdx.x;
    const int khalf = tid & 1;                       // K half: [0,32) or [32,64)
    const int p     = tid >> 1;                      // gate-pair id in [0,128)
    const int g0    = p;                             // first gate row
    const int g1    = p + 128;                       // second gate row
    const int bbase = blockIdx.x * NB;

    // Two half-rows of W_hh in registers: 2 x 16 packed fp32 pairs (64 regs)
    unsigned long long wA[16], wB[16];
    {
        const unsigned long long* wpA = (const unsigned long long*)(W_hh + (size_t)g0 * HH + khalf * 32);
        const unsigned long long* wpB = (const unsigned long long*)(W_hh + (size_t)g1 * HH + khalf * 32);
        #pragma unroll
        for (int j = 0; j < 16; j++){ wA[j] = wpA[j]; wB[j] = wpB[j]; }
    }
    // Input-proj: khalf 0 takes x0,x1 (+bias); khalf 1 takes x2,x3
    const unsigned long long wihA = pack2(W_ih[g0*4 + 2*khalf], W_ih[g0*4 + 2*khalf + 1]);
    const unsigned long long wihB = pack2(W_ih[g1*4 + 2*khalf], W_ih[g1*4 + 2*khalf + 1]);
    const unsigned long long biasA = khalf ? 0ull : pack2(b_ih[g0] + b_hh[g0], 0.f);
    const unsigned long long biasB = khalf ? 0ull : pack2(b_ih[g1] + b_hh[g1], 0.f);

    // Cell update: 448 items over 256 threads.
    //   item1 = tid          -> batches 0..3
    //   item2 = tid + 256    -> batches 4..6  (only tid < 192)
    const int b0u = tid >> 6;
    const int h0u = tid & 63;
    const int b1u = 4 + b0u;
    const bool has2 = (tid < (NB - 4) * HH);         // tid < 192
    float c0 = 0.f, c1 = 0.f;

    // init h = 0; zero x_sh (OOB rows read zeros); preload x for t=0
    for (int i = tid; i < NB * HH; i += NT) ((float*)h_sh)[i] = 0.f;
    if (tid < 2 * NB) ((float4*)x_sh)[tid] = make_float4(0.f, 0.f, 0.f, 0.f);
    __syncthreads();
    if (tid < NB && (bbase + tid) < BB)
        x_sh[0][tid] = ((const float4*)x)[ (size_t)(bbase + tid) * TT ];
    __syncthreads();

    for (int t = 0; t < TT; t++){
        // prefetch next x (latency hidden under GEMV)
        float4 xnext;
        const bool pre = (tid < NB) && (t + 1 < TT) && ((bbase + tid) < BB);
        if (pre) xnext = ((const float4*)x)[ (size_t)(bbase + tid) * TT + (t + 1) ];

        const unsigned long long* xcur = (const unsigned long long*)x_sh[t & 1];

        // ---- gate GEMV over this thread's K half; pair-reduce via shfl ----
        #pragma unroll
        for (int b = 0; b < NB; b++){
            const ulonglong2* hp = (const ulonglong2*)(h_sh[b] + (khalf << 5));  // broadcast LDS.128
            unsigned long long xq = xcur[2*b + khalf];    // x pair for this K half
            unsigned long long aA0 = biasA, aA1 = 0ull, aA2 = 0ull, aA3 = 0ull;
            unsigned long long aB0 = biasB, aB1 = 0ull, aB2 = 0ull, aB3 = 0ull;
            fma2(aA0, wihA, xq);
            fma2(aB0, wihB, xq);
            #pragma unroll
            for (int j = 0; j < 4; j++){
                ulonglong2 hv0 = hp[2*j];
                ulonglong2 hv1 = hp[2*j + 1];
                fma2(aA0, wA[4*j + 0], hv0.x);
                fma2(aA1, wA[4*j + 1], hv0.y);
                fma2(aA2, wA[4*j + 2], hv1.x);
                fma2(aA3, wA[4*j + 3], hv1.y);
                fma2(aB0, wB[4*j + 0], hv0.x);
                fma2(aB1, wB[4*j + 1], hv0.y);
                fma2(aB2, wB[4*j + 2], hv1.x);
                fma2(aB3, wB[4*j + 3], hv1.y);
            }
            float2 fA = unpack2(add2(add2(aA0, aA1), add2(aA2, aA3)));
            float2 fB = unpack2(add2(add2(aB0, aB1), add2(aB2, aB3)));
            float sumA = fA.x + fA.y;
            float sumB = fB.x + fB.y;
            sumA += __shfl_xor_sync(0xffffffffu, sumA, 1);   // combine K halves
            sumB += __shfl_xor_sync(0xffffffffu, sumB, 1);
            if (!khalf){
                g_sh[b][g0] = sumA;
                g_sh[b][g1] = sumB;
            }
        }
        if (pre) x_sh[(t + 1) & 1][tid] = xnext;
        __syncthreads();

        // ---- LSTM cell update: up to 2 items/thread (448 items total) ----
        {
            float gi = g_sh[b0u][h0u];
            float gf = g_sh[b0u][HH   + h0u];
            float gg = g_sh[b0u][2*HH + h0u];
            float go = g_sh[b0u][3*HH + h0u];
            float gi1, gf1, gg1, go1;
            if (has2){
                gi1 = g_sh[b1u][h0u];
                gf1 = g_sh[b1u][HH   + h0u];
                gg1 = g_sh[b1u][2*HH + h0u];
                go1 = g_sh[b1u][3*HH + h0u];
            }
            c0 = sig_ap(gf) * c0 + sig_ap(gi) * tanh_ap(gg);
            h_sh[b0u][h0u] = sig_ap(go) * tanh_ap(c0);
            if (has2){
                c1 = sig_ap(gf1) * c1 + sig_ap(gi1) * tanh_ap(gg1);
                h_sh[b1u][h0u] = sig_ap(go1) * tanh_ap(c1);
            }
        }
        __syncthreads();
    }

    // ---- FC head: 28 outputs ----
    if (tid < NB * OO){
        const int b = tid >> 2, o = tid & 3;
        if ((bbase + b) < BB){
            float s = b_fc[o];
            #pragma unroll
            for (int k = 0; k < HH; k++)
                s = __fmaf_rn(W_fc[o*HH + k], h_sh[b][k], s);
            out[(size_t)(bbase + b) * OO + o] = s;
        }
    }
}

extern "C" void kernel_launch(void* const* d_in, const int* in_sizes, int n_in,
                              void* d_out, int out_size)
{
    const float* x    = (const float*)d_in[0];
    const float* W_ih = (const float*)d_in[1];
    const float* W_hh = (const float*)d_in[2];
    const float* b_ih = (const float*)d_in[3];
    const float* b_hh = (const float*)d_in[4];
    const float* W_fc = (const float*)d_in[5];
    const float* b_fc = (const float*)d_in[6];
    float* out = (float*)d_out;

    lstm_fused_kernel<<<GRID, NT>>>(x, W_ih, W_hh, b_ih, b_hh, W_fc, b_fc, out);
}

// round 6
// speedup vs baseline: 1.0845x; 1.0845x over previous
#include <cuda_runtime.h>
#include <cuda_bf16.h>

// Problem constants: B=2048, T=512, I=4, H=64, O=4
#define TT 512
#define BB 2048
#define HH 64
#define GG 256   // 4*H gates
#define OO 4
#define NB 5     // batch rows per block
#define GRID 444 // exactly 3 blocks per SM on 148 SMs
#define NT 128   // threads per block = gate pairs

// ---- packed fp32x2 ops (Blackwell) ----
__device__ __forceinline__ void fma2(unsigned long long &a, unsigned long long w, unsigned long long h){
    asm("fma.rn.f32x2 %0, %1, %2, %0;" : "+l"(a) : "l"(w), "l"(h));
}
__device__ __forceinline__ unsigned long long add2(unsigned long long a, unsigned long long b){
    unsigned long long r; asm("add.rn.f32x2 %0, %1, %2;" : "=l"(r) : "l"(a), "l"(b)); return r;
}
__device__ __forceinline__ float2 unpack2(unsigned long long v){
    float2 r; asm("mov.b64 {%0, %1}, %2;" : "=f"(r.x), "=f"(r.y) : "l"(v)); return r;
}
__device__ __forceinline__ unsigned long long pack2(float lo, float hi){
    unsigned long long r; asm("mov.b64 %0, {%1, %2};" : "=l"(r) : "f"(lo), "f"(hi)); return r;
}
// ---- native MUFU tanh + sigmoid via tanh ----
__device__ __forceinline__ float tanh_ap(float x){
    float r; asm("tanh.approx.f32 %0, %1;" : "=f"(r) : "f"(x)); return r;
}
__device__ __forceinline__ float sig_ap(float x){
    return __fmaf_rn(0.5f, tanh_ap(0.5f * x), 0.5f);
}

__global__ void __launch_bounds__(NT, 3) lstm_fused_kernel(
    const float* __restrict__ x,     // [B, T, I]
    const float* __restrict__ W_ih,  // [4H, I]
    const float* __restrict__ W_hh,  // [4H, H]
    const float* __restrict__ b_ih,  // [4H]
    const float* __restrict__ b_hh,  // [4H]
    const float* __restrict__ W_fc,  // [O, H]
    const float* __restrict__ b_fc,  // [O]
    float* __restrict__ out)         // [1, B, O]
{
    __shared__ __align__(16) float h_sh[NB][HH];     // hidden state
    __shared__ __align__(16) float g_sh[NB][GG];     // pre-activation gates
    __shared__ __align__(16) float4 x_sh[2][NB];     // double-buffered x_t

    const int tid   = threadIdx.x;                   // gate pair id p in [0,128)
    const int g0    = tid;                           // first gate row
    const int g1    = tid + 128;                     // second gate row
    const int bbase = blockIdx.x * NB;

    // Two W_hh rows in registers: 2 x 32 packed fp32 pairs (128 regs)
    unsigned long long wA[32], wB[32];
    {
        const unsigned long long* wpA = (const unsigned long long*)(W_hh + (size_t)g0 * HH);
        const unsigned long long* wpB = (const unsigned long long*)(W_hh + (size_t)g1 * HH);
        #pragma unroll
        for (int j = 0; j < 32; j++){ wA[j] = wpA[j]; wB[j] = wpB[j]; }
    }
    const unsigned long long wihA01 = pack2(W_ih[g0*4 + 0], W_ih[g0*4 + 1]);
    const unsigned long long wihA23 = pack2(W_ih[g0*4 + 2], W_ih[g0*4 + 3]);
    const unsigned long long wihB01 = pack2(W_ih[g1*4 + 0], W_ih[g1*4 + 1]);
    const unsigned long long wihB23 = pack2(W_ih[g1*4 + 2], W_ih[g1*4 + 3]);
    const unsigned long long biasA  = pack2(b_ih[g0] + b_hh[g0], 0.f);
    const unsigned long long biasB  = pack2(b_ih[g1] + b_hh[g1], 0.f);

    // Cell update: 320 items over 128 threads (items tid, tid+128, tid+256 for tid<64)
    float c0 = 0.f, c1 = 0.f, c2 = 0.f;

    // init h = 0; zero x_sh (OOB rows read zeros); preload x for t=0
    for (int i = tid; i < NB * HH; i += NT) ((float*)h_sh)[i] = 0.f;
    if (tid < 2 * NB) ((float4*)x_sh)[tid] = make_float4(0.f, 0.f, 0.f, 0.f);
    __syncthreads();
    if (tid < NB && (bbase + tid) < BB)
        x_sh[0][tid] = ((const float4*)x)[ (size_t)(bbase + tid) * TT ];
    __syncthreads();

    for (int t = 0; t < TT; t++){
        // prefetch next x (latency hidden under GEMV)
        float4 xnext;
        const bool pre = (tid < NB) && (t + 1 < TT) && ((bbase + tid) < BB);
        if (pre) xnext = ((const float4*)x)[ (size_t)(bbase + tid) * TT + (t + 1) ];

        const ulonglong2* xcur = (const ulonglong2*)x_sh[t & 1];

        // ---- gate GEMV: both gate rows share each h load; 4 accumulator chains ----
        #pragma unroll
        for (int b = 0; b < NB; b++){
            const ulonglong2* hp = (const ulonglong2*)h_sh[b];   // broadcast LDS.128
            ulonglong2 xv = xcur[b];
            unsigned long long aA0 = biasA, aA1 = 0ull;
            unsigned long long aB0 = biasB, aB1 = 0ull;
            fma2(aA0, wihA01, xv.x);  fma2(aA1, wihA23, xv.y);
            fma2(aB0, wihB01, xv.x);  fma2(aB1, wihB23, xv.y);
            #pragma unroll
            for (int j = 0; j < 8; j++){
                ulonglong2 hv0 = hp[2*j];
                ulonglong2 hv1 = hp[2*j + 1];
                fma2(aA0, wA[4*j + 0], hv0.x);
                fma2(aA1, wA[4*j + 1], hv0.y);
                fma2(aB0, wB[4*j + 0], hv0.x);
                fma2(aB1, wB[4*j + 1], hv0.y);
                fma2(aA0, wA[4*j + 2], hv1.x);
                fma2(aA1, wA[4*j + 3], hv1.y);
                fma2(aB0, wB[4*j + 2], hv1.x);
                fma2(aB1, wB[4*j + 3], hv1.y);
            }
            float2 fA = unpack2(add2(aA0, aA1));
            float2 fB = unpack2(add2(aB0, aB1));
            g_sh[b][g0] = fA.x + fA.y;
            g_sh[b][g1] = fB.x + fB.y;
        }
        if (pre) x_sh[(t + 1) & 1][tid] = xnext;
        __syncthreads();

        // ---- LSTM cell update: 320 items, up to 3 per thread ----
        {
            {
                int b = tid >> 6, h = tid & 63;                  // b 0..1
                float gi = g_sh[b][h], gf = g_sh[b][HH+h], gg = g_sh[b][2*HH+h], go = g_sh[b][3*HH+h];
                c0 = sig_ap(gf) * c0 + sig_ap(gi) * tanh_ap(gg);
                h_sh[b][h] = sig_ap(go) * tanh_ap(c0);
            }
            {
                int i = tid + 128;
                int b = i >> 6, h = i & 63;                      // b 2..3
                float gi = g_sh[b][h], gf = g_sh[b][HH+h], gg = g_sh[b][2*HH+h], go = g_sh[b][3*HH+h];
                c1 = sig_ap(gf) * c1 + sig_ap(gi) * tanh_ap(gg);
                h_sh[b][h] = sig_ap(go) * tanh_ap(c1);
            }
            if (tid < 64){
                int h = tid;                                     // b 4
                float gi = g_sh[4][h], gf = g_sh[4][HH+h], gg = g_sh[4][2*HH+h], go = g_sh[4][3*HH+h];
                c2 = sig_ap(gf) * c2 + sig_ap(gi) * tanh_ap(gg);
                h_sh[4][h] = sig_ap(go) * tanh_ap(c2);
            }
        }
        __syncthreads();
    }

    // ---- FC head: 20 outputs ----
    if (tid < NB * OO){
        const int b = tid >> 2, o = tid & 3;
        if ((bbase + b) < BB){
            float s = b_fc[o];
            #pragma unroll
            for (int k = 0; k < HH; k++)
                s = __fmaf_rn(W_fc[o*HH + k], h_sh[b][k], s);
            out[(size_t)(bbase + b) * OO + o] = s;
        }
    }
}

extern "C" void kernel_launch(void* const* d_in, const int* in_sizes, int n_in,
                              void* d_out, int out_size)
{
    const float* x    = (const float*)d_in[0];
    const float* W_ih = (const float*)d_in[1];
    const float* W_hh = (const float*)d_in[2];
    const float* b_ih = (const float*)d_in[3];
    const float* b_hh = (const float*)d_in[4];
    const float* W_fc = (const float*)d_in[5];
    const float* b_fc = (const float*)d_in[6];
    float* out = (float*)d_out;

    lstm_fused_kernel<<<GRID, NT>>>(x, W_ih, W_hh, b_ih, b_hh, W_fc, b_fc, out);
}

// round 7
// speedup vs baseline: 1.1719x; 1.0805x over previous
#include <cuda_runtime.h>
#include <cuda_bf16.h>

// Problem constants: B=2048, T=512, I=4, H=64, O=4
#define TT 512
#define BB 2048
#define HH 64
#define GG 256   // 4*H gates
#define OO 4
#define NB 7     // batch rows per block
#define GRID 296 // 2 blocks per SM on 148 SMs
#define NT 128   // threads per block = gate pairs

// ---- packed fp32x2 ops (Blackwell) ----
__device__ __forceinline__ void fma2(unsigned long long &a, unsigned long long w, unsigned long long h){
    asm("fma.rn.f32x2 %0, %1, %2, %0;" : "+l"(a) : "l"(w), "l"(h));
}
__device__ __forceinline__ unsigned long long add2(unsigned long long a, unsigned long long b){
    unsigned long long r; asm("add.rn.f32x2 %0, %1, %2;" : "=l"(r) : "l"(a), "l"(b)); return r;
}
__device__ __forceinline__ float2 unpack2(unsigned long long v){
    float2 r; asm("mov.b64 {%0, %1}, %2;" : "=f"(r.x), "=f"(r.y) : "l"(v)); return r;
}
__device__ __forceinline__ unsigned long long pack2(float lo, float hi){
    unsigned long long r; asm("mov.b64 %0, {%1, %2};" : "=l"(r) : "f"(lo), "f"(hi)); return r;
}
// ---- native MUFU tanh + sigmoid via tanh ----
__device__ __forceinline__ float tanh_ap(float x){
    float r; asm("tanh.approx.f32 %0, %1;" : "=f"(r) : "f"(x)); return r;
}
__device__ __forceinline__ float sig_ap(float x){
    return __fmaf_rn(0.5f, tanh_ap(0.5f * x), 0.5f);
}

__global__ void __launch_bounds__(NT, 2) lstm_fused_kernel(
    const float* __restrict__ x,     // [B, T, I]
    const float* __restrict__ W_ih,  // [4H, I]
    const float* __restrict__ W_hh,  // [4H, H]
    const float* __restrict__ b_ih,  // [4H]
    const float* __restrict__ b_hh,  // [4H]
    const float* __restrict__ W_fc,  // [O, H]
    const float* __restrict__ b_fc,  // [O]
    float* __restrict__ out)         // [1, B, O]
{
    __shared__ __align__(16) float h_sh[NB][HH];      // hidden state
    __shared__ __align__(16) float ag_sh[NB][HH][4];  // ACTIVATED gates, [b][h][{i,f,g,o}]
    __shared__ __align__(16) float4 x_sh[2][NB];      // double-buffered x_t

    const int tid   = threadIdx.x;                    // gate pair id in [0,128)
    const int g0    = tid;                            // row tid:      i (tid<64) / f (tid>=64)
    const int g1    = tid + 128;                      // row tid+128:  g (tid<64) / o (tid>=64)
    const int bbase = blockIdx.x * NB;
    const int htype = tid >> 6;                       // 0 -> (i,g), 1 -> (f,o)
    const int hrow  = tid & 63;                       // hidden index of my rows
    const bool rowB_is_tanh = (htype == 0);           // row g1 is 'g' gate -> tanh

    // Two W_hh rows in registers: 2 x 32 packed fp32 pairs (128 regs)
    unsigned long long wA[32], wB[32];
    {
        const unsigned long long* wpA = (const unsigned long long*)(W_hh + (size_t)g0 * HH);
        const unsigned long long* wpB = (const unsigned long long*)(W_hh + (size_t)g1 * HH);
        #pragma unroll
        for (int j = 0; j < 32; j++){ wA[j] = wpA[j]; wB[j] = wpB[j]; }
    }
    const unsigned long long wihA01 = pack2(W_ih[g0*4 + 0], W_ih[g0*4 + 1]);
    const unsigned long long wihA23 = pack2(W_ih[g0*4 + 2], W_ih[g0*4 + 3]);
    const unsigned long long wihB01 = pack2(W_ih[g1*4 + 0], W_ih[g1*4 + 1]);
    const unsigned long long wihB23 = pack2(W_ih[g1*4 + 2], W_ih[g1*4 + 3]);
    const unsigned long long biasA  = pack2(b_ih[g0] + b_hh[g0], 0.f);
    const unsigned long long biasB  = pack2(b_ih[g1] + b_hh[g1], 0.f);

    // Cell update: 448 items over 128 threads: tid, tid+128, tid+256, tid+384 (tid<64)
    float c0 = 0.f, c1 = 0.f, c2 = 0.f, c3 = 0.f;

    // init h = 0; zero x_sh (OOB rows read zeros); preload x for t=0
    for (int i = tid; i < NB * HH; i += NT) ((float*)h_sh)[i] = 0.f;
    if (tid < 2 * NB) ((float4*)x_sh)[tid] = make_float4(0.f, 0.f, 0.f, 0.f);
    __syncthreads();
    if (tid < NB && (bbase + tid) < BB)
        x_sh[0][tid] = ((const float4*)x)[ (size_t)(bbase + tid) * TT ];
    __syncthreads();

    for (int t = 0; t < TT; t++){
        // prefetch next x (latency hidden under GEMV)
        float4 xnext;
        const bool pre = (tid < NB) && (t + 1 < TT) && ((bbase + tid) < BB);
        if (pre) xnext = ((const float4*)x)[ (size_t)(bbase + tid) * TT + (t + 1) ];

        const ulonglong2* xcur = (const ulonglong2*)x_sh[t & 1];

        // ---- gate GEMV + activation (activation overlaps next b's FMA chains) ----
        #pragma unroll
        for (int b = 0; b < NB; b++){
            const ulonglong2* hp = (const ulonglong2*)h_sh[b];   // broadcast LDS.128
            ulonglong2 xv = xcur[b];
            unsigned long long aA0 = biasA, aA1 = 0ull, aA2 = 0ull, aA3 = 0ull;
            unsigned long long aB0 = biasB, aB1 = 0ull, aB2 = 0ull, aB3 = 0ull;
            fma2(aA0, wihA01, xv.x);  fma2(aA1, wihA23, xv.y);
            fma2(aB0, wihB01, xv.x);  fma2(aB1, wihB23, xv.y);
            #pragma unroll
            for (int j = 0; j < 8; j++){
                ulonglong2 hv0 = hp[2*j];
                ulonglong2 hv1 = hp[2*j + 1];
                fma2(aA0, wA[4*j + 0], hv0.x);
                fma2(aA1, wA[4*j + 1], hv0.y);
                fma2(aA2, wA[4*j + 2], hv1.x);
                fma2(aA3, wA[4*j + 3], hv1.y);
                fma2(aB0, wB[4*j + 0], hv0.x);
                fma2(aB1, wB[4*j + 1], hv0.y);
                fma2(aB2, wB[4*j + 2], hv1.x);
                fma2(aB3, wB[4*j + 3], hv1.y);
            }
            float2 fA = unpack2(add2(add2(aA0, aA1), add2(aA2, aA3)));
            float2 fB = unpack2(add2(add2(aB0, aB1), add2(aB2, aB3)));
            float sumA = fA.x + fA.y;
            float sumB = fB.x + fB.y;
            // Row A is i or f -> sigmoid. Row B is g (tanh) for tid<64, o (sigmoid) otherwise.
            float actA = sig_ap(sumA);
            float actB = rowB_is_tanh ? tanh_ap(sumB) : sig_ap(sumB);
            ag_sh[b][hrow][htype]     = actA;   // i (0) or f (1)
            ag_sh[b][hrow][2 + htype] = actB;   // g (2) or o (3)
        }
        if (pre) x_sh[(t + 1) & 1][tid] = xnext;
        __syncthreads();

        // ---- LSTM cell update: short chain, one LDS.128 per item ----
        {
            {
                int b = tid >> 6, h = tid & 63;                       // b 0..1
                float4 gv = *(const float4*)ag_sh[b][h];              // i,f,g,o (activated)
                c0 = __fmaf_rn(gv.y, c0, gv.x * gv.z);
                h_sh[b][h] = gv.w * tanh_ap(c0);
            }
            {
                int i = tid + 128, b = i >> 6, h = i & 63;            // b 2..3
                float4 gv = *(const float4*)ag_sh[b][h];
                c1 = __fmaf_rn(gv.y, c1, gv.x * gv.z);
                h_sh[b][h] = gv.w * tanh_ap(c1);
            }
            {
                int i = tid + 256, b = i >> 6, h = i & 63;            // b 4..5
                float4 gv = *(const float4*)ag_sh[b][h];
                c2 = __fmaf_rn(gv.y, c2, gv.x * gv.z);
                h_sh[b][h] = gv.w * tanh_ap(c2);
            }
            if (tid < 64){
                int h = tid;                                          // b 6
                float4 gv = *(const float4*)ag_sh[6][h];
                c3 = __fmaf_rn(gv.y, c3, gv.x * gv.z);
                h_sh[6][h] = gv.w * tanh_ap(c3);
            }
        }
        __syncthreads();
    }

    // ---- FC head: 28 outputs ----
    if (tid < NB * OO){
        const int b = tid >> 2, o = tid & 3;
        if ((bbase + b) < BB){
            float s = b_fc[o];
            #pragma unroll
            for (int k = 0; k < HH; k++)
                s = __fmaf_rn(W_fc[o*HH + k], h_sh[b][k], s);
            out[(size_t)(bbase + b) * OO + o] = s;
        }
    }
}

extern "C" void kernel_launch(void* const* d_in, const int* in_sizes, int n_in,
                              void* d_out, int out_size)
{
    const float* x    = (const float*)d_in[0];
    const float* W_ih = (const float*)d_in[1];
    const float* W_hh = (const float*)d_in[2];
    const float* b_ih = (const float*)d_in[3];
    const float* b_hh = (const float*)d_in[4];
    const float* W_fc = (const float*)d_in[5];
    const float* b_fc = (const float*)d_in[6];
    float* out = (float*)d_out;

    lstm_fused_kernel<<<GRID, NT>>>(x, W_ih, W_hh, b_ih, b_hh, W_fc, b_fc, out);
}

// round 8
// speedup vs baseline: 1.2917x; 1.1022x over previous
#include <cuda_runtime.h>
#include <cuda_bf16.h>

// Problem constants: B=2048, T=512, I=4, H=64, O=4
#define TT 512
#define BB 2048
#define HH 64
#define GG 256   // 4*H gates
#define OO 4
#define NB 7     // batch rows per block (group A = 0..3, group B = 4..6)
#define GRID 296 // 2 blocks per SM on 148 SMs
#define NT 128   // threads per block = gate pairs

// ---- packed fp32x2 ops (Blackwell) ----
__device__ __forceinline__ void fma2(unsigned long long &a, unsigned long long w, unsigned long long h){
    asm("fma.rn.f32x2 %0, %1, %2, %0;" : "+l"(a) : "l"(w), "l"(h));
}
__device__ __forceinline__ unsigned long long add2(unsigned long long a, unsigned long long b){
    unsigned long long r; asm("add.rn.f32x2 %0, %1, %2;" : "=l"(r) : "l"(a), "l"(b)); return r;
}
__device__ __forceinline__ float2 unpack2(unsigned long long v){
    float2 r; asm("mov.b64 {%0, %1}, %2;" : "=f"(r.x), "=f"(r.y) : "l"(v)); return r;
}
__device__ __forceinline__ unsigned long long pack2(float lo, float hi){
    unsigned long long r; asm("mov.b64 %0, {%1, %2};" : "=l"(r) : "f"(lo), "f"(hi)); return r;
}
// ---- native MUFU tanh + sigmoid via tanh ----
__device__ __forceinline__ float tanh_ap(float x){
    float r; asm("tanh.approx.f32 %0, %1;" : "=f"(r) : "f"(x)); return r;
}
__device__ __forceinline__ float sig_ap(float x){
    return __fmaf_rn(0.5f, tanh_ap(0.5f * x), 0.5f);
}

__global__ void __launch_bounds__(NT, 2) lstm_fused_kernel(
    const float* __restrict__ x,     // [B, T, I]
    const float* __restrict__ W_ih,  // [4H, I]
    const float* __restrict__ W_hh,  // [4H, H]
    const float* __restrict__ b_ih,  // [4H]
    const float* __restrict__ b_hh,  // [4H]
    const float* __restrict__ W_fc,  // [O, H]
    const float* __restrict__ b_fc,  // [O]
    float* __restrict__ out)         // [1, B, O]
{
    __shared__ __align__(16) float h_sh[NB][HH];     // hidden state
    __shared__ __align__(16) float g_sh[NB][GG];     // pre-activation gates
    __shared__ __align__(16) float4 x_sh[2][NB];     // double-buffered x_t

    const int tid   = threadIdx.x;                   // gate pair id in [0,128)
    const int g0    = tid;
    const int g1    = tid + 128;
    const int bbase = blockIdx.x * NB;

    // Two W_hh rows in registers: 2 x 32 packed fp32 pairs (128 regs)
    unsigned long long wA[32], wB[32];
    {
        const unsigned long long* wpA = (const unsigned long long*)(W_hh + (size_t)g0 * HH);
        const unsigned long long* wpB = (const unsigned long long*)(W_hh + (size_t)g1 * HH);
        #pragma unroll
        for (int j = 0; j < 32; j++){ wA[j] = wpA[j]; wB[j] = wpB[j]; }
    }
    const unsigned long long wihA01 = pack2(W_ih[g0*4 + 0], W_ih[g0*4 + 1]);
    const unsigned long long wihA23 = pack2(W_ih[g0*4 + 2], W_ih[g0*4 + 3]);
    const unsigned long long wihB01 = pack2(W_ih[g1*4 + 0], W_ih[g1*4 + 1]);
    const unsigned long long wihB23 = pack2(W_ih[g1*4 + 2], W_ih[g1*4 + 3]);
    const unsigned long long biasA  = pack2(b_ih[g0] + b_hh[g0], 0.f);
    const unsigned long long biasB  = pack2(b_ih[g1] + b_hh[g1], 0.f);

// GEMV for one batch row b, reading x pair xv, writing g_sh[b][*]
#define GEMV_ONE(b, xv)                                                        \
    {                                                                          \
        const ulonglong2* hp = (const ulonglong2*)h_sh[(b)];                   \
        unsigned long long aA0 = biasA, aA1 = 0ull, aA2 = 0ull, aA3 = 0ull;    \
        unsigned long long aB0 = biasB, aB1 = 0ull, aB2 = 0ull, aB3 = 0ull;    \
        fma2(aA0, wihA01, (xv).x);  fma2(aA1, wihA23, (xv).y);                 \
        fma2(aB0, wihB01, (xv).x);  fma2(aB1, wihB23, (xv).y);                 \
        _Pragma("unroll")                                                      \
        for (int j = 0; j < 8; j++){                                           \
            ulonglong2 hv0 = hp[2*j];                                          \
            ulonglong2 hv1 = hp[2*j + 1];                                      \
            fma2(aA0, wA[4*j + 0], hv0.x);                                     \
            fma2(aA1, wA[4*j + 1], hv0.y);                                     \
            fma2(aA2, wA[4*j + 2], hv1.x);                                     \
            fma2(aA3, wA[4*j + 3], hv1.y);                                     \
            fma2(aB0, wB[4*j + 0], hv0.x);                                     \
            fma2(aB1, wB[4*j + 1], hv0.y);                                     \
            fma2(aB2, wB[4*j + 2], hv1.x);                                     \
            fma2(aB3, wB[4*j + 3], hv1.y);                                     \
        }                                                                      \
        float2 fA = unpack2(add2(add2(aA0, aA1), add2(aA2, aA3)));             \
        float2 fB = unpack2(add2(add2(aB0, aB1), add2(aB2, aB3)));             \
        g_sh[(b)][g0] = fA.x + fA.y;                                           \
        g_sh[(b)][g1] = fB.x + fB.y;                                           \
    }

// Cell update for item (b,h) with cell register c
#define CELL_ONE(b, h, c)                                                      \
    {                                                                          \
        float gi = g_sh[(b)][(h)];                                             \
        float gf = g_sh[(b)][HH   + (h)];                                      \
        float gg = g_sh[(b)][2*HH + (h)];                                      \
        float go = g_sh[(b)][3*HH + (h)];                                      \
        (c) = sig_ap(gf) * (c) + sig_ap(gi) * tanh_ap(gg);                     \
        h_sh[(b)][(h)] = sig_ap(go) * tanh_ap((c));                            \
    }

    // Cell registers.
    // Group A (b 0..3, 256 items): items tid, tid+128  -> cA0 (b 0..1), cA1 (b 2..3)
    // Group B (b 4..6, 192 items): item tid -> cB0 (b 4..5), item tid+128 (tid<64) -> cB1 (b 6)
    const int bA0 = tid >> 6,      hA0 = tid & 63;
    const int bA1 = 2 + (tid >> 6);
    const int bB0 = 4 + (tid >> 6);
    const bool hasB1 = (tid < 64);
    float cA0 = 0.f, cA1 = 0.f, cB0 = 0.f, cB1 = 0.f;

    // init h = 0; zero x_sh (OOB rows read zeros); preload x for t=0
    for (int i = tid; i < NB * HH; i += NT) ((float*)h_sh)[i] = 0.f;
    if (tid < 2 * NB) ((float4*)x_sh)[tid] = make_float4(0.f, 0.f, 0.f, 0.f);
    __syncthreads();
    if (tid < NB && (bbase + tid) < BB)
        x_sh[0][tid] = ((const float4*)x)[ (size_t)(bbase + tid) * TT ];
    __syncthreads();

    // ---- Prologue: GEMV group A at t=0 ----
    {
        const ulonglong2* xc = (const ulonglong2*)x_sh[0];
        #pragma unroll
        for (int b = 0; b < 4; b++){ ulonglong2 xv = xc[b]; GEMV_ONE(b, xv); }
    }
    __syncthreads();

    for (int t = 0; t < TT; t++){
        // prefetch next x
        float4 xnext;
        const bool pre = (tid < NB) && (t + 1 < TT) && ((bbase + tid) < BB);
        if (pre) xnext = ((const float4*)x)[ (size_t)(bbase + tid) * TT + (t + 1) ];

        // ===== phase 1: GEMV(B, t) + cell(A, t) =====
        {
            const ulonglong2* xc = (const ulonglong2*)x_sh[t & 1];
            #pragma unroll
            for (int b = 4; b < NB; b++){ ulonglong2 xv = xc[b]; GEMV_ONE(b, xv); }
            CELL_ONE(bA0, hA0, cA0);
            CELL_ONE(bA1, hA0, cA1);
        }
        if (pre) x_sh[(t + 1) & 1][tid] = xnext;
        __syncthreads();

        // ===== phase 2: GEMV(A, t+1) + cell(B, t) =====
        {
            if (t + 1 < TT){
                const ulonglong2* xc = (const ulonglong2*)x_sh[(t + 1) & 1];
                #pragma unroll
                for (int b = 0; b < 4; b++){ ulonglong2 xv = xc[b]; GEMV_ONE(b, xv); }
            }
            CELL_ONE(bB0, hA0, cB0);
            if (hasB1) CELL_ONE(6, tid, cB1);
        }
        __syncthreads();
    }

    // ---- FC head: 28 outputs ----
    if (tid < NB * OO){
        const int b = tid >> 2, o = tid & 3;
        if ((bbase + b) < BB){
            float s = b_fc[o];
            #pragma unroll
            for (int k = 0; k < HH; k++)
                s = __fmaf_rn(W_fc[o*HH + k], h_sh[b][k], s);
            out[(size_t)(bbase + b) * OO + o] = s;
        }
    }
}

extern "C" void kernel_launch(void* const* d_in, const int* in_sizes, int n_in,
                              void* d_out, int out_size)
{
    const float* x    = (const float*)d_in[0];
    const float* W_ih = (const float*)d_in[1];
    const float* W_hh = (const float*)d_in[2];
    const float* b_ih = (const float*)d_in[3];
    const float* b_hh = (const float*)d_in[4];
    const float* W_fc = (const float*)d_in[5];
    const float* b_fc = (const float*)d_in[6];
    float* out = (float*)d_out;

    lstm_fused_kernel<<<GRID, NT>>>(x, W_ih, W_hh, b_ih, b_hh, W_fc, b_fc, out);
}